// round 17
// baseline (speedup 1.0000x reference)
#include <cuda_runtime.h>
#include <math.h>
#include <float.h>

// Problem constants (from reference setup_inputs)
#define BB 16
#define KK 32768
#define NN 64
#define CC 21
#define RPB 256                         // threads per block (8 warps)
#define NW  (RPB / 32)
#define ROWS 512                        // rows per block (64 per warp)
#define GRID ((BB * KK) / ROWS)         // 1024 blocks
#define WCONF (64 * CC)                 // floats per warp conf region (1344)
#define WBYTES (WCONF * 4)              // 5376 B per warp (16B-aligned)
#define CSEG 24                         // compacted segments cached per warp
#define EPSF 1.1920929e-07f

__device__ double g_sl = 0.0;
__device__ double g_sc = 0.0;
__device__ unsigned long long g_sp = 0ull;
__device__ unsigned int g_ticket = 0;   // self-resetting via atomicInc wrap

__global__ void __launch_bounds__(RPB, 5) msl_kernel(
    const float* __restrict__ loc_data,   // (B,K,2)
    const float* __restrict__ conf_data,  // (B,K,C)
    const float* __restrict__ priors,     // (K,2)
    const float* __restrict__ truths,     // (B,N,2)
    const int*   __restrict__ labels_raw, // (B,N) int32 or int64 (auto-detect)
    const int*   __restrict__ clip_raw,   // scalar (int/float bits) or null
    float* __restrict__ out)
{
    __shared__ __align__(16) float s_conf[NW * WCONF];      // 43008 B
    __shared__ __align__(8) unsigned long long s_mbar[NW];  // 1 mbarrier per warp
    __shared__ float2        s_cseg[NW * CSEG];             // 1536 B
    __shared__ unsigned char s_clab[NW * CSEG];             // 192 B
    __shared__ float  s_red_l[NW];
    __shared__ float  s_red_c[NW];
    __shared__ int    s_red_p[NW];
    __shared__ int    s_islast;

    const int tid  = threadIdx.x;
    const int warp = tid >> 5;
    const int lane = tid & 31;
    const int row0 = blockIdx.x * ROWS;
    const int b = row0 / KK;             // whole block within one batch
    const int lrowA = warp * 64 + lane;  // warp owns rows [warp*64, +64)
    const int rowA  = row0 + lrowA;
    const int rowB  = rowA + 32;
    const int kA    = rowA - b * KK;

    // clip_length: handle int32 / int64-low-word / float32 encodings
    float cl = 256.0f;
    if (clip_raw) {
        int vi = clip_raw[0];
        float vf = __int_as_float(vi);
        cl = (vi > 0 && vi <= (1 << 20)) ? (float)vi : vf;
    }
    const float maxn = 2.0f * cl;

    // ---- per-warp TMA bulk copy of the warp's 64-row conf slice ----
    const unsigned mbar_a = (unsigned)__cvta_generic_to_shared(&s_mbar[warp]);
    const float* wconf = s_conf + warp * WCONF;
    const unsigned dst_a  = (unsigned)__cvta_generic_to_shared(wconf);
    const float* gsrc = conf_data + (size_t)(row0 + warp * 64) * CC;
    if (lane == 0) {
        asm volatile("mbarrier.init.shared.b64 [%0], 1;" :: "r"(mbar_a) : "memory");
        asm volatile("fence.proxy.async.shared::cta;" ::: "memory");
        asm volatile("mbarrier.arrive.expect_tx.shared.b64 _, [%0], %1;"
                     :: "r"(mbar_a), "r"((unsigned)WBYTES) : "memory");
        asm volatile("cp.async.bulk.shared::cta.global.mbarrier::complete_tx::bytes"
                     " [%0], [%1], %2, [%3];"
                     :: "r"(dst_a), "l"(gsrc), "r"((unsigned)WBYTES), "r"(mbar_a)
                     : "memory");
    }

    // ---- scalar loads (in flight alongside the bulk copy) ----
    const float cenA = __ldg(&priors[2 * kA]);
    const float cenB = __ldg(&priors[2 * (kA + 32)]);
    const float2 pA = ((const float2*)loc_data)[rowA];
    const float2 pB = ((const float2*)loc_data)[rowB];
    const float2 tA = ((const float2*)truths)[b * NN + lane];
    const float2 tB = ((const float2*)truths)[b * NN + lane + 32];
    const bool is64 = (__ldg(&labels_raw[1]) == 0);  // labels >= 1 always
    const int labA = is64 ? __ldg(&labels_raw[2 * (b * NN + lane)])
                          : __ldg(&labels_raw[b * NN + lane]);
    const int labB = is64 ? __ldg(&labels_raw[2 * (b * NN + lane + 32)])
                          : __ldg(&labels_raw[b * NN + lane + 32]);

    // ---- warp min/max of its 64 centers ----
    float mn = fminf(cenA, cenB), mx = fmaxf(cenA, cenB);
    #pragma unroll
    for (int o = 16; o > 0; o >>= 1) {
        mn = fminf(mn, __shfl_xor_sync(0xffffffffu, mn, o));
        mx = fmaxf(mx, __shfl_xor_sync(0xffffffffu, mx, o));
    }

    // ---- warp-local compaction of intersecting segments (order-preserving) ----
    const bool vA = (tA.y >= mn) && (tA.x <= mx);
    const bool vB = (tB.y >= mn) && (tB.x <= mx);
    const unsigned bA  = __ballot_sync(0xffffffffu, vA);
    const unsigned bBv = __ballot_sync(0xffffffffu, vB);
    const unsigned ltm = (1u << lane) - 1u;
    const int cntA = __popc(bA);
    float2* wseg = s_cseg + warp * CSEG;
    unsigned char* wlab = s_clab + warp * CSEG;
    if (vA) {
        int p = __popc(bA & ltm);
        if (p < CSEG) { wseg[p] = tA; wlab[p] = (unsigned char)labA; }
    }
    if (vB) {
        int p = cntA + __popc(bBv & ltm);
        if (p < CSEG) { wseg[p] = tB; wlab[p] = (unsigned char)labB; }
    }
    const int m = cntA + __popc(bBv);
    __syncwarp();                        // compaction STS visible to warp

    int confA = 0, confB = 0;
    float t0A = 0.f, t1A = 0.f, t0B = 0.f, t1B = 0.f;

    if (m <= CSEG) {
        // ---- fast path: argmin over m cached candidates (first-index tie) ----
        float bestA = maxn, bestB = maxn;
        int bnA = 0, bnB = 0;
        #pragma unroll 4
        for (int n = 0; n < m; n++) {
            float2 sg = wseg[n];
            float len = (sg.y - sg.x) * cl;
            bool okA = (cenA >= sg.x) && (cenA <= sg.y);
            bool okB = (cenB >= sg.x) && (cenB <= sg.y);
            float cAv = okA ? len : maxn;
            float cBv = okB ? len : maxn;
            if (cAv < bestA) { bestA = cAv; bnA = n; }
            if (cBv < bestB) { bestB = cBv; bnB = n; }
        }
        if (m > 0) {
            float2 sA = wseg[bnA], sB = wseg[bnB];
            t0A = sA.x; t1A = sA.y; t0B = sB.x; t1B = sB.y;
            confA = (bestA >= maxn) ? 0 : (int)wlab[bnA];
            confB = (bestB >= maxn) ? 0 : (int)wlab[bnB];
        }
    } else {
        // ---- overflow fallback (never taken for bench data): full scan ----
        float bestA = maxn, bestB = maxn;
        int bnA = 0, bnB = 0;
        for (int n = 0; n < NN; n++) {
            float2 sg = ((const float2*)truths)[b * NN + n];
            float len = (sg.y - sg.x) * cl;
            bool okA = (cenA >= sg.x) && (cenA <= sg.y);
            bool okB = (cenB >= sg.x) && (cenB <= sg.y);
            float cAv = okA ? len : maxn;
            float cBv = okB ? len : maxn;
            if (cAv < bestA) { bestA = cAv; bnA = n;
                               t0A = sg.x; t1A = sg.y; }
            if (cBv < bestB) { bestB = cBv; bnB = n;
                               t0B = sg.x; t1B = sg.y; }
        }
        confA = (bestA >= maxn) ? 0
              : (is64 ? __ldg(&labels_raw[2 * (b * NN + bnA)])
                      : __ldg(&labels_raw[b * NN + bnA]));
        confB = (bestB >= maxn) ? 0
              : (is64 ? __ldg(&labels_raw[2 * (b * NN + bnB)])
                      : __ldg(&labels_raw[b * NN + bnB]));
    }

    // ---- GIoU loss for positives ----
    float ll = 0.0f;
    if (confA > 0) {
        float tl = (cenA - t0A) * cl;
        float tr = (t1A - cenA) * cl;
        float inter = fminf(pA.x, tl) + fminf(pA.y, tr);
        float uni = (pA.x + pA.y) + (tl + tr) - inter;
        float ious = __fdividef(inter, fmaxf(uni, EPSF));
        float ac = fmaxf(pA.x, tl) + fmaxf(pA.y, tr);
        ll += 1.0f - (ious - __fdividef(ac - uni, fmaxf(ac, EPSF)));
    }
    if (confB > 0) {
        float tl = (cenB - t0B) * cl;
        float tr = (t1B - cenB) * cl;
        float inter = fminf(pB.x, tl) + fminf(pB.y, tr);
        float uni = (pB.x + pB.y) + (tl + tr) - inter;
        float ious = __fdividef(inter, fmaxf(uni, EPSF));
        float ac = fmaxf(pB.x, tl) + fmaxf(pB.y, tr);
        ll += 1.0f - (ious - __fdividef(ac - uni, fmaxf(ac, EPSF)));
    }
    const int posflag = (confA > 0) + (confB > 0);

    // ---- wait for the warp's bulk copy, then softmax ----
    {
        unsigned done;
        asm volatile(
            "{\n\t"
            ".reg .pred p;\n\t"
            "WAIT_%=:\n\t"
            "mbarrier.try_wait.parity.shared.b64 p, [%1], 0, 0x989680;\n\t"
            "selp.b32 %0, 1, 0, p;\n\t"
            "@!p bra WAIT_%=;\n\t"
            "}"
            : "=r"(done) : "r"(mbar_a) : "memory");
    }
    __syncwarp();

    // ---- focal loss: 4 independent exp/add chains (2 per row) for ILP ----
    const float* crowA = wconf + lane * CC;
    const float* crowB = crowA + 32 * CC;
    float a0 = 0.0f, a1 = 0.0f, b0 = 0.0f, b1 = 0.0f;
    #pragma unroll
    for (int c = 0; c < CC - 1; c += 2) {
        a0 += __expf(crowA[c]);
        b0 += __expf(crowB[c]);
        a1 += __expf(crowA[c + 1]);
        b1 += __expf(crowB[c + 1]);
    }
    const float etA = __expf(crowA[confA]);
    const float etB = __expf(crowB[confB]);
    const float sumA = a0 + a1 + __expf(crowA[CC - 1]);
    const float sumB = b0 + b1 + __expf(crowB[CC - 1]);
    float ptA = __fdividef(etA, sumA) + 1e-6f;
    float ptB = __fdividef(etB, sumB) + 1e-6f;
    float aA = (confA == 0) ? 0.25f : 0.75f;
    float aB = (confB == 0) ? 0.25f : 0.75f;
    float omA = 1.0f - ptA;
    float omB = 1.0f - ptB;
    float lc = -omA * omA * aA * __logf(ptA) - omB * omB * aB * __logf(ptB);

    // ---- block reduction ----
    float v0 = ll, v1 = lc;
    int vp = posflag;
    #pragma unroll
    for (int o = 16; o > 0; o >>= 1) {
        v0 += __shfl_down_sync(0xffffffffu, v0, o);
        v1 += __shfl_down_sync(0xffffffffu, v1, o);
        vp += __shfl_down_sync(0xffffffffu, vp, o);
    }
    if (lane == 0) {
        s_red_l[warp] = v0;
        s_red_c[warp] = v1;
        s_red_p[warp] = vp;
    }
    __syncthreads();
    if (tid == 0) {
        float r0 = 0.0f, r1 = 0.0f;
        int rp = 0;
        #pragma unroll
        for (int w = 0; w < NW; w++) { r0 += s_red_l[w]; r1 += s_red_c[w]; rp += s_red_p[w]; }
        atomicAdd(&g_sl, (double)r0);
        atomicAdd(&g_sc, (double)r1);
        atomicAdd(&g_sp, (unsigned long long)rp);
        __threadfence();
        unsigned int old = atomicInc(&g_ticket, GRID - 1);  // wraps: replay-safe
        s_islast = (old == GRID - 1);
    }
    __syncthreads();

    // ---- last block: finalize from 3 scalars, then reset for next replay ----
    if (s_islast && tid == 0) {
        double sl = *(volatile double*)&g_sl;
        double sc = *(volatile double*)&g_sc;
        unsigned long long sp = *(volatile unsigned long long*)&g_sp;
        double np = (sp > 0ull) ? (double)sp : 1.0;
        out[0] = (float)(sl / np);
        out[1] = (float)(sc / np);
        *(volatile double*)&g_sl = 0.0;
        *(volatile double*)&g_sc = 0.0;
        *(volatile unsigned long long*)&g_sp = 0ull;
    }
}

extern "C" void kernel_launch(void* const* d_in, const int* in_sizes, int n_in,
                              void* d_out, int out_size) {
    const float* loc_data  = (const float*)d_in[0];
    const float* conf_data = (const float*)d_in[1];
    const float* priors    = (const float*)d_in[2];
    const float* truths    = (const float*)d_in[3];
    const int*   labels    = (const int*)d_in[4];
    const int*   clip      = (n_in >= 6) ? (const int*)d_in[5] : nullptr;

    msl_kernel<<<GRID, RPB>>>(loc_data, conf_data, priors, truths, labels,
                              clip, (float*)d_out);
}